// round 4
// baseline (speedup 1.0000x reference)
#include <cuda_runtime.h>
#include <cstdint>

typedef unsigned long long ull;

#define EMB 128
#define INT_EMB 64
#define NRAD 6
#define NSR 42
#define BASIS 8
#define E_EDGES 262144
#define T_TRIP 2097152

// ---------------- scratch (device globals) ------------------------------------
__device__ float g_Wr[NRAD*EMB];
__device__ float g_xji[(size_t)E_EDGES*EMB];
__device__ float g_tmp[(size_t)E_EDGES*EMB];
__device__ float g_upd[(size_t)E_EDGES*EMB];
__device__ float g_xkj2[(size_t)E_EDGES*INT_EMB];
__device__ float g_agg[(size_t)E_EDGES*INT_EMB];

// ---------------- helpers ------------------------------------------------------
__device__ __forceinline__ float silu_f(float x){ return x * (1.0f/(1.0f + __expf(-x))); }
__device__ __forceinline__ uint32_t to_tf32(float f){
    uint32_t u; asm("cvt.rna.tf32.f32 %0, %1;" : "=r"(u) : "f"(f)); return u;
}
__device__ __forceinline__ void mma_tf32(float* c, const uint32_t* a, const uint32_t* b){
    asm volatile("mma.sync.aligned.m16n8k8.row.col.f32.tf32.tf32.f32 "
        "{%0,%1,%2,%3}, {%4,%5,%6,%7}, {%8,%9}, {%0,%1,%2,%3};"
        : "+f"(c[0]), "+f"(c[1]), "+f"(c[2]), "+f"(c[3])
        : "r"(a[0]), "r"(a[1]), "r"(a[2]), "r"(a[3]), "r"(b[0]), "r"(b[1]));
}

// Fragment-ready SMEM layout:
//  A[row][k]  -> Af[((s*MT + mt)*32 + lane)*4 + reg]
//     s=k>>3, mt=row>>4, rr=row&15, cc=k&7
//     lane = ((rr&7)<<2)|(cc&3),  reg = ((cc>>2)<<1)|(rr>>3)
//  W[k][n]    -> Bf[((s*NT + nt)*32 + lane)*2 + reg]
//     s=k>>3, nt=n>>3, kk=k&7, nn=n&7
//     lane = (nn<<2)|(kk&3),     reg = kk>>2

// ---------------- K0: fuse W_rbf1 @ W_rbf2 -> g_Wr ----------------------------
__global__ void fuse_wr_kernel(const float* __restrict__ W1, const float* __restrict__ W2) {
    int i = blockIdx.x * blockDim.x + threadIdx.x;
    if (i < NRAD * EMB) {
        int r = i / EMB, n = i % EMB;
        float s = 0.f;
#pragma unroll
        for (int b = 0; b < BASIS; b++) s += W1[r*BASIS + b] * W2[b*EMB + n];
        g_Wr[i] = s;
    }
}

// ---------------- zero g_agg --------------------------------------------------
__global__ void zero_agg_kernel() {
    size_t i = (size_t)blockIdx.x * blockDim.x + threadIdx.x;
    float4 z = {0.f, 0.f, 0.f, 0.f};
    ((float4*)g_agg)[i] = z;
}

// ---------------- staging helpers ---------------------------------------------
template<int K>
__device__ __forceinline__ void stage_A(const float* __restrict__ A, size_t m0,
                                        uint32_t* __restrict__ Af, int tid) {
    constexpr int MT = 8;
    for (int i = tid; i < 128*(K/4); i += 256) {
        int row = i / (K/4);
        int c = (i % (K/4)) * 4;
        const float4 a4 = *(const float4*)&A[(m0+row)*K + c];
        float v[4] = {a4.x, a4.y, a4.z, a4.w};
        int mt = row >> 4, rr = row & 15;
#pragma unroll
        for (int e = 0; e < 4; e++) {
            int k = c + e, cc = k & 7, s = k >> 3;
            int ln = ((rr & 7) << 2) | (cc & 3);
            int rg = ((cc >> 2) << 1) | (rr >> 3);
            Af[((s*MT + mt)*32 + ln)*4 + rg] = to_tf32(v[e]);
        }
    }
}
template<int K, int N>
__device__ __forceinline__ void stage_B(const float* __restrict__ W,
                                        uint32_t* __restrict__ Bf, int tid) {
    constexpr int NT = N/8;
    for (int i = tid; i < K*(N/4); i += 256) {
        int k = i / (N/4);
        int n = (i % (N/4)) * 4;
        const float4 b4 = *(const float4*)&W[(size_t)k*N + n];
        float v[4] = {b4.x, b4.y, b4.z, b4.w};
        int s = k >> 3, kk = k & 7, rg = kk >> 2;
#pragma unroll
        for (int e = 0; e < 4; e++) {
            int nn = (n+e) & 7, nt = (n+e) >> 3;
            int ln = (nn << 2) | (kk & 3);
            Bf[((s*NT + nt)*32 + ln)*2 + rg] = to_tf32(v[e]);
        }
    }
}

// ---------------- generic fused GEMM (tf32 mma.sync) ---------------------------
// out = [res +] silu(A@W [+ bias]) [* rbf_env]
template<int N, int K, bool MUL_RBF, bool ADD_RES>
__global__ __launch_bounds__(256, 1)
void gemm_mma(const float* __restrict__ A, const float* __restrict__ W,
              const float* __restrict__ bias, const float* __restrict__ res,
              const float* __restrict__ rbf, float* __restrict__ out) {
    constexpr int KS = K/8, MT = 8, NT = N/8;
    constexpr int WMT = (N == 128) ? 2 : 1;   // m-tiles per warp
    constexpr int WNT = 8;                    // n-tiles per warp
    extern __shared__ __align__(16) uint32_t dyn[];
    uint32_t* Af = dyn;                    // KS*MT*32*4
    uint32_t* Bf = dyn + KS*MT*32*4;       // KS*NT*32*2
    __shared__ float s_Wr[MUL_RBF ? NRAD*EMB : 1];

    const int tid = threadIdx.x, lane = tid & 31, w = tid >> 5;
    const size_t m0 = (size_t)blockIdx.x * 128;
    const int mt0 = (N == 128) ? (w >> 1) * 2 : w;
    const int nt0 = (N == 128) ? (w & 1) * 8 : 0;

    if (MUL_RBF) for (int i = tid; i < NRAD*EMB; i += 256) s_Wr[i] = g_Wr[i];

    stage_A<K>(A, m0, Af, tid);
    stage_B<K, N>(W, Bf, tid);
    __syncthreads();

    float acc[WMT][WNT][4];
#pragma unroll
    for (int i = 0; i < WMT; i++)
#pragma unroll
        for (int j = 0; j < WNT; j++)
#pragma unroll
            for (int e = 0; e < 4; e++) acc[i][j][e] = 0.f;

#pragma unroll
    for (int s = 0; s < KS; s++) {
        uint4 af[WMT]; uint2 bf[WNT];
#pragma unroll
        for (int i = 0; i < WMT; i++)
            af[i] = *(const uint4*)&Af[((s*MT + mt0 + i)*32 + lane)*4];
#pragma unroll
        for (int j = 0; j < WNT; j++)
            bf[j] = *(const uint2*)&Bf[((s*NT + nt0 + j)*32 + lane)*2];
#pragma unroll
        for (int i = 0; i < WMT; i++)
#pragma unroll
            for (int j = 0; j < WNT; j++)
                mma_tf32(acc[i][j], (const uint32_t*)&af[i], (const uint32_t*)&bf[j]);
    }

    // epilogue
#pragma unroll
    for (int i = 0; i < WMT; i++) {
        const size_t r_lo = m0 + (mt0 + i)*16 + (lane >> 2);
        const size_t r_hi = r_lo + 8;
        float r6lo[NRAD], r6hi[NRAD];
        if (MUL_RBF) {
#pragma unroll
            for (int l = 0; l < NRAD; l++) { r6lo[l] = rbf[r_lo*NRAD + l]; r6hi[l] = rbf[r_hi*NRAD + l]; }
        }
#pragma unroll
        for (int j = 0; j < WNT; j++) {
            const int col = (nt0 + j)*8 + (lane & 3)*2;
            float2 bj = make_float2(0.f, 0.f);
            if (bias) bj = *(const float2*)&bias[col];
            float v00 = silu_f(acc[i][j][0] + bj.x);
            float v01 = silu_f(acc[i][j][1] + bj.y);
            float v10 = silu_f(acc[i][j][2] + bj.x);
            float v11 = silu_f(acc[i][j][3] + bj.y);
            if (MUL_RBF) {
                float e00=0.f,e01=0.f,e10=0.f,e11=0.f;
#pragma unroll
                for (int l = 0; l < NRAD; l++) {
                    const float w0 = s_Wr[l*EMB + col], w1 = s_Wr[l*EMB + col + 1];
                    e00 += r6lo[l]*w0; e01 += r6lo[l]*w1;
                    e10 += r6hi[l]*w0; e11 += r6hi[l]*w1;
                }
                v00 *= e00; v01 *= e01; v10 *= e10; v11 *= e11;
            }
            if (ADD_RES) {
                const float2 rl = *(const float2*)&res[r_lo*N + col];
                const float2 rh = *(const float2*)&res[r_hi*N + col];
                v00 += rl.x; v01 += rl.y; v10 += rh.x; v11 += rh.y;
            }
            float2 o0; o0.x = v00; o0.y = v01;
            float2 o1; o1.x = v10; o1.y = v11;
            *(float2*)&out[r_lo*N + col] = o0;
            *(float2*)&out[r_hi*N + col] = o1;
        }
    }
}

// ---------------- fused residual block: out = x + silu(silu(x@W1+b1)@W2+b2) ----
__global__ __launch_bounds__(256, 1)
void resid_mma(const float* __restrict__ X, const float* __restrict__ W1,
               const float* __restrict__ b1, const float* __restrict__ W2,
               const float* __restrict__ b2, float* __restrict__ out) {
    constexpr int KS = 16, MT = 8, NT = 16, WMT = 2, WNT = 8;
    extern __shared__ __align__(16) uint32_t dyn[];
    uint32_t* Af  = dyn;            // 16384 u32
    uint32_t* B1f = dyn + 16384;    // 16384 u32
    uint32_t* B2f = dyn + 32768;    // 16384 u32

    const int tid = threadIdx.x, lane = tid & 31, w = tid >> 5;
    const size_t m0 = (size_t)blockIdx.x * 128;
    const int mt0 = (w >> 1) * 2;
    const int nt0 = (w & 1) * 8;

    stage_A<128>(X, m0, Af, tid);
    stage_B<128,128>(W1, B1f, tid);
    stage_B<128,128>(W2, B2f, tid);
    __syncthreads();

    float acc[WMT][WNT][4];
#pragma unroll
    for (int i = 0; i < WMT; i++)
#pragma unroll
        for (int j = 0; j < WNT; j++)
#pragma unroll
            for (int e = 0; e < 4; e++) acc[i][j][e] = 0.f;

    // ---- GEMM1: acc = X @ W1 ----
#pragma unroll
    for (int s = 0; s < KS; s++) {
        uint4 af[WMT]; uint2 bf[WNT];
#pragma unroll
        for (int i = 0; i < WMT; i++)
            af[i] = *(const uint4*)&Af[((s*MT + mt0 + i)*32 + lane)*4];
#pragma unroll
        for (int j = 0; j < WNT; j++)
            bf[j] = *(const uint2*)&B1f[((s*NT + nt0 + j)*32 + lane)*2];
#pragma unroll
        for (int i = 0; i < WMT; i++)
#pragma unroll
            for (int j = 0; j < WNT; j++)
                mma_tf32(acc[i][j], (const uint32_t*)&af[i], (const uint32_t*)&bf[j]);
    }
    __syncthreads();   // all warps done reading Af

    // ---- epilogue1: h = silu(acc + b1), write back into Af as fragments ----
#pragma unroll
    for (int j = 0; j < WNT; j++) {
        const int s2  = nt0 + j;            // k-step index of h column group
        const int cc0 = (lane & 3) * 2;     // col within group (even)
        const float2 bj = *(const float2*)&b1[s2*8 + cc0];
#pragma unroll
        for (int i = 0; i < WMT; i++) {
            const int rl = (mt0 + i)*16 + (lane >> 2);  // local row (lo)
            float v[4];
            v[0] = silu_f(acc[i][j][0] + bj.x);  // (rl,   cc0)
            v[1] = silu_f(acc[i][j][1] + bj.y);  // (rl,   cc0+1)
            v[2] = silu_f(acc[i][j][2] + bj.x);  // (rl+8, cc0)
            v[3] = silu_f(acc[i][j][3] + bj.y);  // (rl+8, cc0+1)
#pragma unroll
            for (int e = 0; e < 4; e++) {
                const int r = rl + ((e >> 1) ? 8 : 0);
                const int cc = cc0 + (e & 1);
                const int rr = r & 15, mt = r >> 4;
                const int ln = ((rr & 7) << 2) | (cc & 3);
                const int rg = ((cc >> 2) << 1) | (rr >> 3);
                Af[((s2*MT + mt)*32 + ln)*4 + rg] = to_tf32(v[e]);
            }
        }
    }
    __syncthreads();

    // ---- GEMM2: acc = h @ W2 ----
#pragma unroll
    for (int i = 0; i < WMT; i++)
#pragma unroll
        for (int j = 0; j < WNT; j++)
#pragma unroll
            for (int e = 0; e < 4; e++) acc[i][j][e] = 0.f;
#pragma unroll
    for (int s = 0; s < KS; s++) {
        uint4 af[WMT]; uint2 bf[WNT];
#pragma unroll
        for (int i = 0; i < WMT; i++)
            af[i] = *(const uint4*)&Af[((s*MT + mt0 + i)*32 + lane)*4];
#pragma unroll
        for (int j = 0; j < WNT; j++)
            bf[j] = *(const uint2*)&B2f[((s*NT + nt0 + j)*32 + lane)*2];
#pragma unroll
        for (int i = 0; i < WMT; i++)
#pragma unroll
            for (int j = 0; j < WNT; j++)
                mma_tf32(acc[i][j], (const uint32_t*)&af[i], (const uint32_t*)&bf[j]);
    }

    // ---- epilogue2: out = X + silu(acc + b2) ----
#pragma unroll
    for (int i = 0; i < WMT; i++) {
        const size_t r_lo = m0 + (mt0 + i)*16 + (lane >> 2);
        const size_t r_hi = r_lo + 8;
#pragma unroll
        for (int j = 0; j < WNT; j++) {
            const int col = (nt0 + j)*8 + (lane & 3)*2;
            const float2 bj = *(const float2*)&b2[col];
            const float2 xl = *(const float2*)&X[r_lo*128 + col];
            const float2 xh = *(const float2*)&X[r_hi*128 + col];
            float2 o0, o1;
            o0.x = xl.x + silu_f(acc[i][j][0] + bj.x);
            o0.y = xl.y + silu_f(acc[i][j][1] + bj.y);
            o1.x = xh.x + silu_f(acc[i][j][2] + bj.x);
            o1.y = xh.y + silu_f(acc[i][j][3] + bj.y);
            *(float2*)&out[r_lo*128 + col] = o0;
            *(float2*)&out[r_hi*128 + col] = o1;
        }
    }
}

// ---------------- triplet kernel (unchanged, passes) ---------------------------
__global__ __launch_bounds__(256)
void triplet_kernel(const float* __restrict__ sbf,
                    const int* __restrict__ src_idx,
                    const int* __restrict__ dst_idx,
                    const float* __restrict__ W1,
                    const float* __restrict__ W2) {
    __shared__ float sbf_s[16*NSR];
    __shared__ float W1s[NSR*BASIS];
    __shared__ __align__(16) float W2s[BASIS*INT_EMB];
    __shared__ float t8[16][BASIS];

    const int tid = threadIdx.x;
    for (int i = tid; i < NSR*BASIS; i += 256) W1s[i] = W1[i];
    for (int i = tid; i < BASIS*INT_EMB; i += 256) W2s[i] = W2[i];

    const int ngroups = T_TRIP / 16;
    const int half = tid >> 4;
    const int l16  = tid & 15;

    for (int g = blockIdx.x; g < ngroups; g += gridDim.x) {
        const size_t base = (size_t)g * (16*NSR);
        for (int i = tid; i < 16*NSR; i += 256) sbf_s[i] = sbf[base + i];
        __syncthreads();

        if (tid < 128) {
            int tt = tid >> 3, j = tid & 7;
            float s = 0.f;
#pragma unroll
            for (int r = 0; r < NSR; r++) s += sbf_s[tt*NSR + r] * W1s[r*BASIS + j];
            t8[tt][j] = s;
        }
        __syncthreads();

        const int t = g*16 + half;
        const int src = src_idx[t];
        const int dst = dst_idx[t];

        float4 a = {0.f, 0.f, 0.f, 0.f};
#pragma unroll
        for (int j = 0; j < BASIS; j++) {
            const float tv = t8[half][j];
            const float4 w = *(const float4*)&W2s[j*INT_EMB + l16*4];
            a.x += tv*w.x; a.y += tv*w.y; a.z += tv*w.z; a.w += tv*w.w;
        }
        const float4 xk = *(const float4*)(g_xkj2 + (size_t)src*INT_EMB + l16*4);
        a.x *= xk.x; a.y *= xk.y; a.z *= xk.z; a.w *= xk.w;

        atomicAdd((float4*)(g_agg + (size_t)dst*INT_EMB + l16*4), a);
        __syncthreads();
    }
}

// ---------------- host launcher ----------------------------------------------
extern "C" void kernel_launch(void* const* d_in, const int* in_sizes, int n_in,
                              void* d_out, int out_size) {
    const float* m       = (const float*)d_in[0];
    const float* rbf     = (const float*)d_in[1];
    const float* sbf     = (const float*)d_in[2];
    const int*   src_idx = (const int*)d_in[3];
    const int*   dst_idx = (const int*)d_in[4];
    const float* W_rbf1  = (const float*)d_in[5];
    const float* W_rbf2  = (const float*)d_in[6];
    const float* W_sbf1  = (const float*)d_in[7];
    const float* W_sbf2  = (const float*)d_in[8];
    const float* W_ji    = (const float*)d_in[9];
    const float* b_ji    = (const float*)d_in[10];
    const float* W_kj    = (const float*)d_in[11];
    const float* b_kj    = (const float*)d_in[12];
    const float* W_down  = (const float*)d_in[13];
    const float* W_up    = (const float*)d_in[14];
    const float* Wb1     = (const float*)d_in[15];
    const float* bb1     = (const float*)d_in[16];
    const float* Wb2     = (const float*)d_in[17];
    const float* bb2     = (const float*)d_in[18];
    const float* W_final = (const float*)d_in[19];
    const float* b_final = (const float*)d_in[20];
    const float* Wa1     = (const float*)d_in[21];
    const float* ba1     = (const float*)d_in[22];
    const float* Wa2     = (const float*)d_in[23];
    const float* ba2     = (const float*)d_in[24];
    float* out = (float*)d_out;

    float *p_xji, *p_tmp, *p_upd, *p_xkj2, *p_agg;
    cudaGetSymbolAddress((void**)&p_xji,  g_xji);
    cudaGetSymbolAddress((void**)&p_tmp,  g_tmp);
    cudaGetSymbolAddress((void**)&p_upd,  g_upd);
    cudaGetSymbolAddress((void**)&p_xkj2, g_xkj2);
    cudaGetSymbolAddress((void**)&p_agg,  g_agg);

    const int GB = E_EDGES / 128;   // 2048

    // dynamic smem bytes: (A frag + B frag) * 4
    const int SM_128_128 = (16*8*32*4 + 16*16*32*2) * 4;  // 131072
    const int SM_64_128  = (16*8*32*4 + 16*8*32*2) * 4;   //  98304
    const int SM_128_64  = (8*8*32*4 + 8*16*32*2) * 4;    //  65536
    const int SM_RESID   = 3 * 65536;                     // 196608

    cudaFuncSetAttribute((const void*)gemm_mma<128,128,false,false>, cudaFuncAttributeMaxDynamicSharedMemorySize, SM_128_128);
    cudaFuncSetAttribute((const void*)gemm_mma<128,128,true ,false>, cudaFuncAttributeMaxDynamicSharedMemorySize, SM_128_128);
    cudaFuncSetAttribute((const void*)gemm_mma<128,128,false,true >, cudaFuncAttributeMaxDynamicSharedMemorySize, SM_128_128);
    cudaFuncSetAttribute((const void*)gemm_mma<64 ,128,false,false>, cudaFuncAttributeMaxDynamicSharedMemorySize, SM_64_128);
    cudaFuncSetAttribute((const void*)gemm_mma<128,64 ,false,true >, cudaFuncAttributeMaxDynamicSharedMemorySize, SM_128_64);
    cudaFuncSetAttribute((const void*)resid_mma, cudaFuncAttributeMaxDynamicSharedMemorySize, SM_RESID);

    // K0: fused rbf weight
    fuse_wr_kernel<<<3, 256>>>(W_rbf1, W_rbf2);
    // zero aggregation buffer
    zero_agg_kernel<<<(E_EDGES*INT_EMB/4)/256, 256>>>();

    // x_ji = silu(m @ W_ji + b_ji)
    gemm_mma<128,128,false,false><<<GB,256,SM_128_128>>>(m, W_ji, b_ji, nullptr, nullptr, p_xji);
    // xkjm = silu(m @ W_kj + b_kj) * rbf_env
    gemm_mma<128,128,true ,false><<<GB,256,SM_128_128>>>(m, W_kj, b_kj, nullptr, rbf, p_tmp);
    // x_kj2 = silu(xkjm @ W_down)
    gemm_mma<64 ,128,false,false><<<GB,256,SM_64_128>>>(p_tmp, W_down, nullptr, nullptr, nullptr, p_xkj2);

    // triplet message + segment sum
    triplet_kernel<<<4096, 256>>>(sbf, src_idx, dst_idx, W_sbf1, W_sbf2);

    // upd = x_ji + silu(agg @ W_up)
    gemm_mma<128,64 ,false,true ><<<GB,256,SM_128_64>>>(p_agg, W_up, nullptr, p_xji, nullptr, p_upd);
    // residual-before (N_BEFORE=1), in-place
    resid_mma<<<GB,256,SM_RESID>>>(p_upd, Wb1, bb1, Wb2, bb2, p_upd);
    // final: out = m + silu(upd @ W_final + b_final)
    gemm_mma<128,128,false,true ><<<GB,256,SM_128_128>>>(p_upd, W_final, b_final, m, nullptr, out);
    // residual-after (N_AFTER=2), in-place on out
    resid_mma<<<GB,256,SM_RESID>>>(out, Wa1,           ba1,       Wa2,           ba2,       out);
    resid_mma<<<GB,256,SM_RESID>>>(out, Wa1 + 128*128, ba1 + 128, Wa2 + 128*128, ba2 + 128, out);
}

// round 6
// speedup vs baseline: 1.7936x; 1.7936x over previous
#include <cuda_runtime.h>
#include <cstdint>

typedef unsigned long long ull;

#define EMB 128
#define INT_EMB 64
#define NRAD 6
#define NSR 42
#define BASIS 8
#define E_EDGES 262144
#define T_TRIP 2097152

// ---------------- scratch (device globals) ------------------------------------
__device__ float g_Wr[NRAD*EMB];
__device__ float g_xji[(size_t)E_EDGES*EMB];
__device__ float g_tmp[(size_t)E_EDGES*EMB];
__device__ float g_upd[(size_t)E_EDGES*EMB];
__device__ float g_xkj2[(size_t)E_EDGES*INT_EMB];
__device__ float g_agg[(size_t)E_EDGES*INT_EMB];
__device__ uint32_t g_Bf[163840];   // all weights, tf32 fragment layout

// B-frag offsets (u32 elements)
#define OFF_JI   0
#define OFF_KJ   16384
#define OFF_DOWN 32768
#define OFF_UP   40960
#define OFF_B1   49152
#define OFF_B2   65536
#define OFF_FIN  81920
#define OFF_A10  98304
#define OFF_A20  114688
#define OFF_A11  131072
#define OFF_A21  147456

// ---------------- helpers ------------------------------------------------------
__device__ __forceinline__ float silu_f(float x){ return x * (1.0f/(1.0f + __expf(-x))); }
__device__ __forceinline__ uint32_t to_tf32(float f){
    uint32_t u; asm("cvt.rna.tf32.f32 %0, %1;" : "=r"(u) : "f"(f)); return u;
}
__device__ __forceinline__ void mma_tf32(float* c, const uint32_t* a, const uint32_t* b){
    asm volatile("mma.sync.aligned.m16n8k8.row.col.f32.tf32.tf32.f32 "
        "{%0,%1,%2,%3}, {%4,%5,%6,%7}, {%8,%9}, {%0,%1,%2,%3};"
        : "+f"(c[0]), "+f"(c[1]), "+f"(c[2]), "+f"(c[3])
        : "r"(a[0]), "r"(a[1]), "r"(a[2]), "r"(a[3]), "r"(b[0]), "r"(b[1]));
}

// ---------------- K0: fuse W_rbf1 @ W_rbf2 -> g_Wr ----------------------------
__global__ void fuse_wr_kernel(const float* __restrict__ W1, const float* __restrict__ W2) {
    int i = blockIdx.x * blockDim.x + threadIdx.x;
    if (i < NRAD * EMB) {
        int r = i / EMB, n = i % EMB;
        float s = 0.f;
#pragma unroll
        for (int b = 0; b < BASIS; b++) s += W1[r*BASIS + b] * W2[b*EMB + n];
        g_Wr[i] = s;
    }
}

// ---------------- zero g_agg --------------------------------------------------
__global__ void zero_agg_kernel() {
    size_t i = (size_t)blockIdx.x * blockDim.x + threadIdx.x;
    float4 z = {0.f, 0.f, 0.f, 0.f};
    ((float4*)g_agg)[i] = z;
}

// ---------------- B fragment precompute (per weight matrix) -------------------
// W[K,N] row-major -> tf32 fragments for mma m16n8k8 col-major B.
// Bf[((s*NT + nt)*32 + lane)*2 + rg]: lane=(nn<<2)|(kk&3), rg=kk>>2.
__global__ void stage_Bg(const float* __restrict__ W, uint32_t* __restrict__ out,
                         int K, int N) {
    int i = blockIdx.x * 128 + threadIdx.x;
    int total = K * (N/4);
    if (i >= total) return;
    int k = i / (N/4), n = (i % (N/4)) * 4;
    const float4 b4 = *(const float4*)&W[(size_t)k*N + n];
    float v[4] = {b4.x, b4.y, b4.z, b4.w};
    int NT = N/8;
    int s = k >> 3, kk = k & 7, rg = kk >> 2;
#pragma unroll
    for (int e = 0; e < 4; e++) {
        int nn = (n+e) & 7, nt = (n+e) >> 3;
        int ln = (nn << 2) | (kk & 3);
        out[((s*NT + nt)*32 + ln)*2 + rg] = to_tf32(v[e]);
    }
}

// ---------------- A staging: row-major, XOR-swizzled, tf32 --------------------
template<int K>
__device__ __forceinline__ void stage_A(const float* __restrict__ A, size_t m0,
                                        uint32_t* __restrict__ As, int tid) {
    constexpr int QPR = K/4;
    for (int i = tid; i < 128*QPR; i += 256) {
        int row = i / QPR, q = i % QPR;
        const float4 a4 = *(const float4*)&A[(m0+row)*K + q*4];
        uint4 t;
        t.x = to_tf32(a4.x); t.y = to_tf32(a4.y); t.z = to_tf32(a4.z); t.w = to_tf32(a4.w);
        int c = (q*4) ^ ((row & 7) << 2);
        *(uint4*)&As[row*K + c] = t;
    }
}

// ---------------- generic fused GEMM (tf32 mma.sync, B frags in gmem) ----------
// out = [res +] silu(A@W [+ bias]) [* rbf_env]
template<int N, int K, bool MUL_RBF, bool ADD_RES>
__global__ __launch_bounds__(256, 2)
void gemm_mma2(const float* __restrict__ A, const uint32_t* __restrict__ Bf,
               const float* __restrict__ bias, const float* __restrict__ res,
               const float* __restrict__ rbf, float* __restrict__ out) {
    constexpr int KS = K/8, NT = N/8, WNT = NT;
    extern __shared__ __align__(16) uint32_t As[];
    __shared__ float s_Wr[MUL_RBF ? NRAD*EMB : 1];

    const int tid = threadIdx.x, lane = tid & 31, w = tid >> 5;
    const size_t m0 = (size_t)blockIdx.x * 128;

    if (MUL_RBF) for (int i = tid; i < NRAD*EMB; i += 256) s_Wr[i] = g_Wr[i];
    stage_A<K>(A, m0, As, tid);
    __syncthreads();

    float acc[WNT][4];
#pragma unroll
    for (int j = 0; j < WNT; j++)
#pragma unroll
        for (int e = 0; e < 4; e++) acc[j][e] = 0.f;

    const int r0 = w*16 + (lane >> 2);
    const int sw = (lane >> 2) << 2;
    const int rowA = r0*K, rowA8 = (r0+8)*K;

#pragma unroll
    for (int s = 0; s < KS; s++) {
        const int c0 = s*8 + (lane & 3);
        uint32_t a[4];
        a[0] = As[rowA  + (c0 ^ sw)];
        a[1] = As[rowA8 + (c0 ^ sw)];
        a[2] = As[rowA  + ((c0+4) ^ sw)];
        a[3] = As[rowA8 + ((c0+4) ^ sw)];
#pragma unroll
        for (int j = 0; j < WNT; j++) {
            uint2 b = *(const uint2*)&Bf[((s*NT + j)*32 + lane)*2];
            mma_tf32(acc[j], a, (const uint32_t*)&b);
        }
    }

    // epilogue
    const size_t r_lo = m0 + r0, r_hi = r_lo + 8;
    float r6lo[NRAD], r6hi[NRAD];
    if (MUL_RBF) {
#pragma unroll
        for (int l = 0; l < NRAD; l++) { r6lo[l] = rbf[r_lo*NRAD + l]; r6hi[l] = rbf[r_hi*NRAD + l]; }
    }
#pragma unroll
    for (int j = 0; j < WNT; j++) {
        const int col = j*8 + (lane & 3)*2;
        float2 bj = make_float2(0.f, 0.f);
        if (bias) bj = *(const float2*)&bias[col];
        float v00 = silu_f(acc[j][0] + bj.x);
        float v01 = silu_f(acc[j][1] + bj.y);
        float v10 = silu_f(acc[j][2] + bj.x);
        float v11 = silu_f(acc[j][3] + bj.y);
        if (MUL_RBF) {
            float e00=0.f,e01=0.f,e10=0.f,e11=0.f;
#pragma unroll
            for (int l = 0; l < NRAD; l++) {
                const float w0 = s_Wr[l*EMB + col], w1 = s_Wr[l*EMB + col + 1];
                e00 += r6lo[l]*w0; e01 += r6lo[l]*w1;
                e10 += r6hi[l]*w0; e11 += r6hi[l]*w1;
            }
            v00 *= e00; v01 *= e01; v10 *= e10; v11 *= e11;
        }
        if (ADD_RES) {
            const float2 rl = *(const float2*)&res[r_lo*N + col];
            const float2 rh = *(const float2*)&res[r_hi*N + col];
            v00 += rl.x; v01 += rl.y; v10 += rh.x; v11 += rh.y;
        }
        float2 o0; o0.x = v00; o0.y = v01;
        float2 o1; o1.x = v10; o1.y = v11;
        *(float2*)&out[r_lo*N + col] = o0;
        *(float2*)&out[r_hi*N + col] = o1;
    }
}

// ---------------- fused residual block: out = x + silu(silu(x@W1+b1)@W2+b2) ----
__global__ __launch_bounds__(256, 2)
void resid_mma2(const float* __restrict__ X,
                const uint32_t* __restrict__ B1f, const float* __restrict__ b1,
                const uint32_t* __restrict__ B2f, const float* __restrict__ b2,
                float* __restrict__ out) {
    constexpr int KS = 16, NT = 16, WNT = 16;
    extern __shared__ __align__(16) uint32_t As[];

    const int tid = threadIdx.x, lane = tid & 31, w = tid >> 5;
    const size_t m0 = (size_t)blockIdx.x * 128;

    stage_A<128>(X, m0, As, tid);
    __syncthreads();

    const int r0 = w*16 + (lane >> 2);
    const int sw = (lane >> 2) << 2;
    const int rowA = r0*128, rowA8 = (r0+8)*128;

    float acc[WNT][4];
#pragma unroll
    for (int j = 0; j < WNT; j++)
#pragma unroll
        for (int e = 0; e < 4; e++) acc[j][e] = 0.f;

    // ---- GEMM1: acc = X @ W1 ----
#pragma unroll
    for (int s = 0; s < KS; s++) {
        const int c0 = s*8 + (lane & 3);
        uint32_t a[4];
        a[0] = As[rowA  + (c0 ^ sw)];
        a[1] = As[rowA8 + (c0 ^ sw)];
        a[2] = As[rowA  + ((c0+4) ^ sw)];
        a[3] = As[rowA8 + ((c0+4) ^ sw)];
#pragma unroll
        for (int j = 0; j < WNT; j++) {
            uint2 b = *(const uint2*)&B1f[((s*NT + j)*32 + lane)*2];
            mma_tf32(acc[j], a, (const uint32_t*)&b);
        }
    }

    // ---- epilogue1: h = silu(acc + b1) -> back into As (warp-local rows) ----
#pragma unroll
    for (int j = 0; j < WNT; j++) {
        const int cj = j*8 + (lane & 3)*2;
        const float2 bj = *(const float2*)&b1[cj];
        float v[4];
        v[0] = silu_f(acc[j][0] + bj.x);
        v[1] = silu_f(acc[j][1] + bj.y);
        v[2] = silu_f(acc[j][2] + bj.x);
        v[3] = silu_f(acc[j][3] + bj.y);
        const int rlo = w*16 + (lane >> 2);
#pragma unroll
        for (int e = 0; e < 4; e++) {
            const int r = rlo + ((e >> 1) ? 8 : 0);
            const int c = cj + (e & 1);
            As[r*128 + (c ^ sw)] = to_tf32(v[e]);
        }
    }
    __syncwarp();

    // ---- GEMM2: acc = h @ W2 ----
#pragma unroll
    for (int j = 0; j < WNT; j++)
#pragma unroll
        for (int e = 0; e < 4; e++) acc[j][e] = 0.f;
#pragma unroll
    for (int s = 0; s < KS; s++) {
        const int c0 = s*8 + (lane & 3);
        uint32_t a[4];
        a[0] = As[rowA  + (c0 ^ sw)];
        a[1] = As[rowA8 + (c0 ^ sw)];
        a[2] = As[rowA  + ((c0+4) ^ sw)];
        a[3] = As[rowA8 + ((c0+4) ^ sw)];
#pragma unroll
        for (int j = 0; j < WNT; j++) {
            uint2 b = *(const uint2*)&B2f[((s*NT + j)*32 + lane)*2];
            mma_tf32(acc[j], a, (const uint32_t*)&b);
        }
    }

    // ---- epilogue2: out = X + silu(acc + b2) ----
    const size_t r_lo = m0 + r0, r_hi = r_lo + 8;
#pragma unroll
    for (int j = 0; j < WNT; j++) {
        const int col = j*8 + (lane & 3)*2;
        const float2 bj = *(const float2*)&b2[col];
        const float2 xl = *(const float2*)&X[r_lo*128 + col];
        const float2 xh = *(const float2*)&X[r_hi*128 + col];
        float2 o0, o1;
        o0.x = xl.x + silu_f(acc[j][0] + bj.x);
        o0.y = xl.y + silu_f(acc[j][1] + bj.y);
        o1.x = xh.x + silu_f(acc[j][2] + bj.x);
        o1.y = xh.y + silu_f(acc[j][3] + bj.y);
        *(float2*)&out[r_lo*128 + col] = o0;
        *(float2*)&out[r_hi*128 + col] = o1;
    }
}

// ---------------- triplet kernel (unchanged, passes) ---------------------------
__global__ __launch_bounds__(256)
void triplet_kernel(const float* __restrict__ sbf,
                    const int* __restrict__ src_idx,
                    const int* __restrict__ dst_idx,
                    const float* __restrict__ W1,
                    const float* __restrict__ W2) {
    __shared__ float sbf_s[16*NSR];
    __shared__ float W1s[NSR*BASIS];
    __shared__ __align__(16) float W2s[BASIS*INT_EMB];
    __shared__ float t8[16][BASIS];

    const int tid = threadIdx.x;
    for (int i = tid; i < NSR*BASIS; i += 256) W1s[i] = W1[i];
    for (int i = tid; i < BASIS*INT_EMB; i += 256) W2s[i] = W2[i];

    const int ngroups = T_TRIP / 16;
    const int half = tid >> 4;
    const int l16  = tid & 15;

    for (int g = blockIdx.x; g < ngroups; g += gridDim.x) {
        const size_t base = (size_t)g * (16*NSR);
        for (int i = tid; i < 16*NSR; i += 256) sbf_s[i] = sbf[base + i];
        __syncthreads();

        if (tid < 128) {
            int tt = tid >> 3, j = tid & 7;
            float s = 0.f;
#pragma unroll
            for (int r = 0; r < NSR; r++) s += sbf_s[tt*NSR + r] * W1s[r*BASIS + j];
            t8[tt][j] = s;
        }
        __syncthreads();

        const int t = g*16 + half;
        const int src = src_idx[t];
        const int dst = dst_idx[t];

        float4 a = {0.f, 0.f, 0.f, 0.f};
#pragma unroll
        for (int j = 0; j < BASIS; j++) {
            const float tv = t8[half][j];
            const float4 w = *(const float4*)&W2s[j*INT_EMB + l16*4];
            a.x += tv*w.x; a.y += tv*w.y; a.z += tv*w.z; a.w += tv*w.w;
        }
        const float4 xk = *(const float4*)(g_xkj2 + (size_t)src*INT_EMB + l16*4);
        a.x *= xk.x; a.y *= xk.y; a.z *= xk.z; a.w *= xk.w;

        atomicAdd((float4*)(g_agg + (size_t)dst*INT_EMB + l16*4), a);
        __syncthreads();
    }
}

// ---------------- host launcher ----------------------------------------------
extern "C" void kernel_launch(void* const* d_in, const int* in_sizes, int n_in,
                              void* d_out, int out_size) {
    const float* m       = (const float*)d_in[0];
    const float* rbf     = (const float*)d_in[1];
    const float* sbf     = (const float*)d_in[2];
    const int*   src_idx = (const int*)d_in[3];
    const int*   dst_idx = (const int*)d_in[4];
    const float* W_rbf1  = (const float*)d_in[5];
    const float* W_rbf2  = (const float*)d_in[6];
    const float* W_sbf1  = (const float*)d_in[7];
    const float* W_sbf2  = (const float*)d_in[8];
    const float* W_ji    = (const float*)d_in[9];
    const float* b_ji    = (const float*)d_in[10];
    const float* W_kj    = (const float*)d_in[11];
    const float* b_kj    = (const float*)d_in[12];
    const float* W_down  = (const float*)d_in[13];
    const float* W_up    = (const float*)d_in[14];
    const float* Wb1     = (const float*)d_in[15];
    const float* bb1     = (const float*)d_in[16];
    const float* Wb2     = (const float*)d_in[17];
    const float* bb2     = (const float*)d_in[18];
    const float* W_final = (const float*)d_in[19];
    const float* b_final = (const float*)d_in[20];
    const float* Wa1     = (const float*)d_in[21];
    const float* ba1     = (const float*)d_in[22];
    const float* Wa2     = (const float*)d_in[23];
    const float* ba2     = (const float*)d_in[24];
    float* out = (float*)d_out;

    float *p_xji, *p_tmp, *p_upd, *p_xkj2, *p_agg;
    uint32_t* p_Bf;
    cudaGetSymbolAddress((void**)&p_xji,  g_xji);
    cudaGetSymbolAddress((void**)&p_tmp,  g_tmp);
    cudaGetSymbolAddress((void**)&p_upd,  g_upd);
    cudaGetSymbolAddress((void**)&p_xkj2, g_xkj2);
    cudaGetSymbolAddress((void**)&p_agg,  g_agg);
    cudaGetSymbolAddress((void**)&p_Bf,   g_Bf);

    const int GB = E_EDGES / 128;     // 2048
    const int SM_K128 = 128*128*4;    // 65536
    const int SM_K64  = 128*64*4;     // 32768

    cudaFuncSetAttribute((const void*)gemm_mma2<128,128,false,false>, cudaFuncAttributeMaxDynamicSharedMemorySize, SM_K128);
    cudaFuncSetAttribute((const void*)gemm_mma2<128,128,true ,false>, cudaFuncAttributeMaxDynamicSharedMemorySize, SM_K128);
    cudaFuncSetAttribute((const void*)gemm_mma2<128,128,false,true >, cudaFuncAttributeMaxDynamicSharedMemorySize, SM_K128);
    cudaFuncSetAttribute((const void*)gemm_mma2<64 ,128,false,false>, cudaFuncAttributeMaxDynamicSharedMemorySize, SM_K128);
    cudaFuncSetAttribute((const void*)gemm_mma2<128,64 ,false,true >, cudaFuncAttributeMaxDynamicSharedMemorySize, SM_K64);
    cudaFuncSetAttribute((const void*)resid_mma2, cudaFuncAttributeMaxDynamicSharedMemorySize, SM_K128);

    // precompute: fused rbf weight + all B fragments + zero agg
    fuse_wr_kernel<<<3, 256>>>(W_rbf1, W_rbf2);
    zero_agg_kernel<<<(E_EDGES*INT_EMB/4)/256, 256>>>();

    stage_Bg<<<128, 128>>>(W_ji,    p_Bf + OFF_JI,   128, 128);
    stage_Bg<<<128, 128>>>(W_kj,    p_Bf + OFF_KJ,   128, 128);
    stage_Bg<<<64 , 128>>>(W_down,  p_Bf + OFF_DOWN, 128, 64);
    stage_Bg<<<64 , 128>>>(W_up,    p_Bf + OFF_UP,   64 , 128);
    stage_Bg<<<128, 128>>>(Wb1,     p_Bf + OFF_B1,   128, 128);
    stage_Bg<<<128, 128>>>(Wb2,     p_Bf + OFF_B2,   128, 128);
    stage_Bg<<<128, 128>>>(W_final, p_Bf + OFF_FIN,  128, 128);
    stage_Bg<<<128, 128>>>(Wa1,           p_Bf + OFF_A10, 128, 128);
    stage_Bg<<<128, 128>>>(Wa2,           p_Bf + OFF_A20, 128, 128);
    stage_Bg<<<128, 128>>>(Wa1 + 128*128, p_Bf + OFF_A11, 128, 128);
    stage_Bg<<<128, 128>>>(Wa2 + 128*128, p_Bf + OFF_A21, 128, 128);

    // x_ji = silu(m @ W_ji + b_ji)
    gemm_mma2<128,128,false,false><<<GB,256,SM_K128>>>(m, p_Bf + OFF_JI, b_ji, nullptr, nullptr, p_xji);
    // xkjm = silu(m @ W_kj + b_kj) * rbf_env
    gemm_mma2<128,128,true ,false><<<GB,256,SM_K128>>>(m, p_Bf + OFF_KJ, b_kj, nullptr, rbf, p_tmp);
    // x_kj2 = silu(xkjm @ W_down)
    gemm_mma2<64 ,128,false,false><<<GB,256,SM_K128>>>(p_tmp, p_Bf + OFF_DOWN, nullptr, nullptr, nullptr, p_xkj2);

    // triplet message + segment sum
    triplet_kernel<<<4096, 256>>>(sbf, src_idx, dst_idx, W_sbf1, W_sbf2);

    // upd = x_ji + silu(agg @ W_up)
    gemm_mma2<128,64 ,false,true ><<<GB,256,SM_K64>>>(p_agg, p_Bf + OFF_UP, nullptr, p_xji, nullptr, p_upd);
    // residual-before (N_BEFORE=1), in-place
    resid_mma2<<<GB,256,SM_K128>>>(p_upd, p_Bf + OFF_B1, bb1, p_Bf + OFF_B2, bb2, p_upd);
    // final: out = m + silu(upd @ W_final + b_final)
    gemm_mma2<128,128,false,true ><<<GB,256,SM_K128>>>(p_upd, p_Bf + OFF_FIN, b_final, m, nullptr, out);
    // residual-after (N_AFTER=2), in-place on out
    resid_mma2<<<GB,256,SM_K128>>>(out, p_Bf + OFF_A10, ba1,       p_Bf + OFF_A20, ba2,       out);
    resid_mma2<<<GB,256,SM_K128>>>(out, p_Bf + OFF_A11, ba1 + 128, p_Bf + OFF_A21, ba2 + 128, out);
}

// round 7
// speedup vs baseline: 1.8702x; 1.0427x over previous
#include <cuda_runtime.h>
#include <cstdint>

typedef unsigned long long ull;

#define EMB 128
#define INT_EMB 64
#define NRAD 6
#define NSR 42
#define BASIS 8
#define E_EDGES 262144
#define T_TRIP 2097152

// ---------------- scratch (device globals) ------------------------------------
__device__ float g_Wr[NRAD*EMB];
__device__ float g_xji[(size_t)E_EDGES*EMB];
__device__ float g_tmp[(size_t)E_EDGES*EMB];
__device__ float g_upd[(size_t)E_EDGES*EMB];
__device__ float g_xkj2[(size_t)E_EDGES*INT_EMB];
__device__ float g_agg[(size_t)E_EDGES*INT_EMB];
__device__ uint32_t g_Bf[163840];   // all weights, tf32 fragment layout

// B-frag offsets (u32 elements)
#define OFF_JI   0
#define OFF_KJ   16384
#define OFF_DOWN 32768
#define OFF_UP   40960
#define OFF_B1   49152
#define OFF_B2   65536
#define OFF_FIN  81920
#define OFF_A10  98304
#define OFF_A20  114688
#define OFF_A11  131072
#define OFF_A21  147456

// ---------------- helpers ------------------------------------------------------
__device__ __forceinline__ float silu_f(float x){ return x * (1.0f/(1.0f + __expf(-x))); }
__device__ __forceinline__ uint32_t to_tf32(float f){
    uint32_t u; asm("cvt.rna.tf32.f32 %0, %1;" : "=r"(u) : "f"(f)); return u;
}
__device__ __forceinline__ void mma_tf32(float* c, const uint32_t* a, const uint32_t* b){
    asm volatile("mma.sync.aligned.m16n8k8.row.col.f32.tf32.tf32.f32 "
        "{%0,%1,%2,%3}, {%4,%5,%6,%7}, {%8,%9}, {%0,%1,%2,%3};"
        : "+f"(c[0]), "+f"(c[1]), "+f"(c[2]), "+f"(c[3])
        : "r"(a[0]), "r"(a[1]), "r"(a[2]), "r"(a[3]), "r"(b[0]), "r"(b[1]));
}

// ---------------- K0: fuse W_rbf1 @ W_rbf2 -> g_Wr ----------------------------
__global__ void fuse_wr_kernel(const float* __restrict__ W1, const float* __restrict__ W2) {
    int i = blockIdx.x * blockDim.x + threadIdx.x;
    if (i < NRAD * EMB) {
        int r = i / EMB, n = i % EMB;
        float s = 0.f;
#pragma unroll
        for (int b = 0; b < BASIS; b++) s += W1[r*BASIS + b] * W2[b*EMB + n];
        g_Wr[i] = s;
    }
}

// ---------------- zero g_agg --------------------------------------------------
__global__ void zero_agg_kernel() {
    size_t i = (size_t)blockIdx.x * blockDim.x + threadIdx.x;
    float4 z = {0.f, 0.f, 0.f, 0.f};
    ((float4*)g_agg)[i] = z;
}

// ---------------- B fragment precompute (per weight matrix) -------------------
__global__ void stage_Bg(const float* __restrict__ W, uint32_t* __restrict__ out,
                         int K, int N) {
    int i = blockIdx.x * 128 + threadIdx.x;
    int total = K * (N/4);
    if (i >= total) return;
    int k = i / (N/4), n = (i % (N/4)) * 4;
    const float4 b4 = *(const float4*)&W[(size_t)k*N + n];
    float v[4] = {b4.x, b4.y, b4.z, b4.w};
    int NT = N/8;
    int s = k >> 3, kk = k & 7, rg = kk >> 2;
#pragma unroll
    for (int e = 0; e < 4; e++) {
        int nn = (n+e) & 7, nt = (n+e) >> 3;
        int ln = (nn << 2) | (kk & 3);
        out[((s*NT + nt)*32 + ln)*2 + rg] = to_tf32(v[e]);
    }
}

// ---------------- A staging: row-major, XOR-swizzled, tf32 --------------------
template<int K>
__device__ __forceinline__ void stage_A(const float* __restrict__ A, size_t m0,
                                        uint32_t* __restrict__ As, int tid) {
    constexpr int QPR = K/4;
    for (int i = tid; i < 128*QPR; i += 256) {
        int row = i / QPR, q = i % QPR;
        const float4 a4 = *(const float4*)&A[(m0+row)*K + q*4];
        uint4 t;
        t.x = to_tf32(a4.x); t.y = to_tf32(a4.y); t.z = to_tf32(a4.z); t.w = to_tf32(a4.w);
        int c = (q*4) ^ ((row & 7) << 2);
        *(uint4*)&As[row*K + c] = t;
    }
}

// ---------------- generic fused GEMM (tf32 mma.sync, WMT=2 x WNT=NT/2) ---------
// out = [res +] silu(A@W [+ bias]) [* rbf_env]
// Warp grid 4(m) x 2(n): warp owns 32 rows x N/2 cols.
template<int N, int K, bool MUL_RBF, bool ADD_RES>
__global__ __launch_bounds__(256, 2)
void gemm_mma3(const float* __restrict__ A, const uint32_t* __restrict__ Bf,
               const float* __restrict__ bias, const float* __restrict__ res,
               const float* __restrict__ rbf, float* __restrict__ out) {
    constexpr int KS = K/8, NT = N/8, WNT = NT/2;
    extern __shared__ __align__(16) uint32_t As[];
    __shared__ float s_Wr[MUL_RBF ? NRAD*EMB : 1];

    const int tid = threadIdx.x, lane = tid & 31, w = tid >> 5;
    const size_t m0 = (size_t)blockIdx.x * 128;
    const int mp = w >> 1;          // 0..3 : rows mp*32 .. mp*32+31
    const int nt0 = (w & 1) * WNT;  // n-tile base

    if (MUL_RBF) for (int i = tid; i < NRAD*EMB; i += 256) s_Wr[i] = g_Wr[i];
    stage_A<K>(A, m0, As, tid);
    __syncthreads();

    float acc[2][WNT][4];
#pragma unroll
    for (int i = 0; i < 2; i++)
#pragma unroll
        for (int j = 0; j < WNT; j++)
#pragma unroll
            for (int e = 0; e < 4; e++) acc[i][j][e] = 0.f;

    const int q = lane >> 2;
    const int sw = q << 2;
    const int rowA0 = (mp*32 + q) * K;        // i=0 lo row
    const int rowA1 = (mp*32 + 16 + q) * K;   // i=1 lo row

#pragma unroll
    for (int s = 0; s < KS; s++) {
        const int c0 = s*8 + (lane & 3);
        uint32_t a[2][4];
        a[0][0] = As[rowA0       + (c0 ^ sw)];
        a[0][1] = As[rowA0 + 8*K + (c0 ^ sw)];
        a[0][2] = As[rowA0       + ((c0+4) ^ sw)];
        a[0][3] = As[rowA0 + 8*K + ((c0+4) ^ sw)];
        a[1][0] = As[rowA1       + (c0 ^ sw)];
        a[1][1] = As[rowA1 + 8*K + (c0 ^ sw)];
        a[1][2] = As[rowA1       + ((c0+4) ^ sw)];
        a[1][3] = As[rowA1 + 8*K + ((c0+4) ^ sw)];
#pragma unroll
        for (int j = 0; j < WNT; j++) {
            uint2 b = *(const uint2*)&Bf[((s*NT + nt0 + j)*32 + lane)*2];
            mma_tf32(acc[0][j], a[0], (const uint32_t*)&b);
            mma_tf32(acc[1][j], a[1], (const uint32_t*)&b);
        }
    }

    // epilogue
#pragma unroll
    for (int i = 0; i < 2; i++) {
        const size_t r_lo = m0 + mp*32 + i*16 + q;
        const size_t r_hi = r_lo + 8;
        float r6lo[NRAD], r6hi[NRAD];
        if (MUL_RBF) {
#pragma unroll
            for (int l = 0; l < NRAD; l++) { r6lo[l] = rbf[r_lo*NRAD + l]; r6hi[l] = rbf[r_hi*NRAD + l]; }
        }
#pragma unroll
        for (int j = 0; j < WNT; j++) {
            const int col = (nt0 + j)*8 + (lane & 3)*2;
            float2 bj = make_float2(0.f, 0.f);
            if (bias) bj = *(const float2*)&bias[col];
            float v00 = silu_f(acc[i][j][0] + bj.x);
            float v01 = silu_f(acc[i][j][1] + bj.y);
            float v10 = silu_f(acc[i][j][2] + bj.x);
            float v11 = silu_f(acc[i][j][3] + bj.y);
            if (MUL_RBF) {
                float e00=0.f,e01=0.f,e10=0.f,e11=0.f;
#pragma unroll
                for (int l = 0; l < NRAD; l++) {
                    const float w0 = s_Wr[l*EMB + col], w1 = s_Wr[l*EMB + col + 1];
                    e00 += r6lo[l]*w0; e01 += r6lo[l]*w1;
                    e10 += r6hi[l]*w0; e11 += r6hi[l]*w1;
                }
                v00 *= e00; v01 *= e01; v10 *= e10; v11 *= e11;
            }
            if (ADD_RES) {
                const float2 rl = *(const float2*)&res[r_lo*N + col];
                const float2 rh = *(const float2*)&res[r_hi*N + col];
                v00 += rl.x; v01 += rl.y; v10 += rh.x; v11 += rh.y;
            }
            float2 o0; o0.x = v00; o0.y = v01;
            float2 o1; o1.x = v10; o1.y = v11;
            *(float2*)&out[r_lo*N + col] = o0;
            *(float2*)&out[r_hi*N + col] = o1;
        }
    }
}

// ---------------- fused residual block: out = x + silu(silu(x@W1+b1)@W2+b2) ----
__global__ __launch_bounds__(256, 2)
void resid_mma3(const float* __restrict__ X,
                const uint32_t* __restrict__ B1f, const float* __restrict__ b1,
                const uint32_t* __restrict__ B2f, const float* __restrict__ b2,
                float* __restrict__ out) {
    constexpr int KS = 16, NT = 16, WNT = 8;
    extern __shared__ __align__(16) uint32_t As[];

    const int tid = threadIdx.x, lane = tid & 31, w = tid >> 5;
    const size_t m0 = (size_t)blockIdx.x * 128;
    const int mp = w >> 1;
    const int nt0 = (w & 1) * WNT;

    stage_A<128>(X, m0, As, tid);
    __syncthreads();

    const int q = lane >> 2;
    const int sw = q << 2;
    const int rowA0 = (mp*32 + q) * 128;
    const int rowA1 = (mp*32 + 16 + q) * 128;

    float acc[2][WNT][4];
#pragma unroll
    for (int i = 0; i < 2; i++)
#pragma unroll
        for (int j = 0; j < WNT; j++)
#pragma unroll
            for (int e = 0; e < 4; e++) acc[i][j][e] = 0.f;

    // ---- GEMM1: acc = X @ W1 ----
#pragma unroll
    for (int s = 0; s < KS; s++) {
        const int c0 = s*8 + (lane & 3);
        uint32_t a[2][4];
        a[0][0] = As[rowA0         + (c0 ^ sw)];
        a[0][1] = As[rowA0 + 8*128 + (c0 ^ sw)];
        a[0][2] = As[rowA0         + ((c0+4) ^ sw)];
        a[0][3] = As[rowA0 + 8*128 + ((c0+4) ^ sw)];
        a[1][0] = As[rowA1         + (c0 ^ sw)];
        a[1][1] = As[rowA1 + 8*128 + (c0 ^ sw)];
        a[1][2] = As[rowA1         + ((c0+4) ^ sw)];
        a[1][3] = As[rowA1 + 8*128 + ((c0+4) ^ sw)];
#pragma unroll
        for (int j = 0; j < WNT; j++) {
            uint2 b = *(const uint2*)&B1f[((s*NT + nt0 + j)*32 + lane)*2];
            mma_tf32(acc[0][j], a[0], (const uint32_t*)&b);
            mma_tf32(acc[1][j], a[1], (const uint32_t*)&b);
        }
    }
    __syncthreads();  // everyone done reading As (GEMM1)

    // ---- epilogue1: h = silu(acc + b1) -> back into As ----
#pragma unroll
    for (int i = 0; i < 2; i++) {
        const int rl = mp*32 + i*16 + q;
#pragma unroll
        for (int j = 0; j < WNT; j++) {
            const int cj = (nt0 + j)*8 + (lane & 3)*2;
            const float2 bj = *(const float2*)&b1[cj];
            float v[4];
            v[0] = silu_f(acc[i][j][0] + bj.x);
            v[1] = silu_f(acc[i][j][1] + bj.y);
            v[2] = silu_f(acc[i][j][2] + bj.x);
            v[3] = silu_f(acc[i][j][3] + bj.y);
#pragma unroll
            for (int e = 0; e < 4; e++) {
                const int r = rl + ((e >> 1) ? 8 : 0);
                const int c = cj + (e & 1);
                As[r*128 + (c ^ sw)] = to_tf32(v[e]);
            }
        }
    }
    __syncthreads();  // h fully written (n-halves cross warps)

    // ---- GEMM2: acc = h @ W2 ----
#pragma unroll
    for (int i = 0; i < 2; i++)
#pragma unroll
        for (int j = 0; j < WNT; j++)
#pragma unroll
            for (int e = 0; e < 4; e++) acc[i][j][e] = 0.f;
#pragma unroll
    for (int s = 0; s < KS; s++) {
        const int c0 = s*8 + (lane & 3);
        uint32_t a[2][4];
        a[0][0] = As[rowA0         + (c0 ^ sw)];
        a[0][1] = As[rowA0 + 8*128 + (c0 ^ sw)];
        a[0][2] = As[rowA0         + ((c0+4) ^ sw)];
        a[0][3] = As[rowA0 + 8*128 + ((c0+4) ^ sw)];
        a[1][0] = As[rowA1         + (c0 ^ sw)];
        a[1][1] = As[rowA1 + 8*128 + (c0 ^ sw)];
        a[1][2] = As[rowA1         + ((c0+4) ^ sw)];
        a[1][3] = As[rowA1 + 8*128 + ((c0+4) ^ sw)];
#pragma unroll
        for (int j = 0; j < WNT; j++) {
            uint2 b = *(const uint2*)&B2f[((s*NT + nt0 + j)*32 + lane)*2];
            mma_tf32(acc[0][j], a[0], (const uint32_t*)&b);
            mma_tf32(acc[1][j], a[1], (const uint32_t*)&b);
        }
    }

    // ---- epilogue2: out = X + silu(acc + b2) ----
#pragma unroll
    for (int i = 0; i < 2; i++) {
        const size_t r_lo = m0 + mp*32 + i*16 + q;
        const size_t r_hi = r_lo + 8;
#pragma unroll
        for (int j = 0; j < WNT; j++) {
            const int col = (nt0 + j)*8 + (lane & 3)*2;
            const float2 bj = *(const float2*)&b2[col];
            const float2 xl = *(const float2*)&X[r_lo*128 + col];
            const float2 xh = *(const float2*)&X[r_hi*128 + col];
            float2 o0, o1;
            o0.x = xl.x + silu_f(acc[i][j][0] + bj.x);
            o0.y = xl.y + silu_f(acc[i][j][1] + bj.y);
            o1.x = xh.x + silu_f(acc[i][j][2] + bj.x);
            o1.y = xh.y + silu_f(acc[i][j][3] + bj.y);
            *(float2*)&out[r_lo*128 + col] = o0;
            *(float2*)&out[r_hi*128 + col] = o1;
        }
    }
}

// ---------------- triplet kernel (unchanged, passes) ---------------------------
__global__ __launch_bounds__(256)
void triplet_kernel(const float* __restrict__ sbf,
                    const int* __restrict__ src_idx,
                    const int* __restrict__ dst_idx,
                    const float* __restrict__ W1,
                    const float* __restrict__ W2) {
    __shared__ float sbf_s[16*NSR];
    __shared__ float W1s[NSR*BASIS];
    __shared__ __align__(16) float W2s[BASIS*INT_EMB];
    __shared__ float t8[16][BASIS];

    const int tid = threadIdx.x;
    for (int i = tid; i < NSR*BASIS; i += 256) W1s[i] = W1[i];
    for (int i = tid; i < BASIS*INT_EMB; i += 256) W2s[i] = W2[i];

    const int ngroups = T_TRIP / 16;
    const int half = tid >> 4;
    const int l16  = tid & 15;

    for (int g = blockIdx.x; g < ngroups; g += gridDim.x) {
        const size_t base = (size_t)g * (16*NSR);
        for (int i = tid; i < 16*NSR; i += 256) sbf_s[i] = sbf[base + i];
        __syncthreads();

        if (tid < 128) {
            int tt = tid >> 3, j = tid & 7;
            float s = 0.f;
#pragma unroll
            for (int r = 0; r < NSR; r++) s += sbf_s[tt*NSR + r] * W1s[r*BASIS + j];
            t8[tt][j] = s;
        }
        __syncthreads();

        const int t = g*16 + half;
        const int src = src_idx[t];
        const int dst = dst_idx[t];

        float4 a = {0.f, 0.f, 0.f, 0.f};
#pragma unroll
        for (int j = 0; j < BASIS; j++) {
            const float tv = t8[half][j];
            const float4 w = *(const float4*)&W2s[j*INT_EMB + l16*4];
            a.x += tv*w.x; a.y += tv*w.y; a.z += tv*w.z; a.w += tv*w.w;
        }
        const float4 xk = *(const float4*)(g_xkj2 + (size_t)src*INT_EMB + l16*4);
        a.x *= xk.x; a.y *= xk.y; a.z *= xk.z; a.w *= xk.w;

        atomicAdd((float4*)(g_agg + (size_t)dst*INT_EMB + l16*4), a);
        __syncthreads();
    }
}

// ---------------- host launcher ----------------------------------------------
extern "C" void kernel_launch(void* const* d_in, const int* in_sizes, int n_in,
                              void* d_out, int out_size) {
    const float* m       = (const float*)d_in[0];
    const float* rbf     = (const float*)d_in[1];
    const float* sbf     = (const float*)d_in[2];
    const int*   src_idx = (const int*)d_in[3];
    const int*   dst_idx = (const int*)d_in[4];
    const float* W_rbf1  = (const float*)d_in[5];
    const float* W_rbf2  = (const float*)d_in[6];
    const float* W_sbf1  = (const float*)d_in[7];
    const float* W_sbf2  = (const float*)d_in[8];
    const float* W_ji    = (const float*)d_in[9];
    const float* b_ji    = (const float*)d_in[10];
    const float* W_kj    = (const float*)d_in[11];
    const float* b_kj    = (const float*)d_in[12];
    const float* W_down  = (const float*)d_in[13];
    const float* W_up    = (const float*)d_in[14];
    const float* Wb1     = (const float*)d_in[15];
    const float* bb1     = (const float*)d_in[16];
    const float* Wb2     = (const float*)d_in[17];
    const float* bb2     = (const float*)d_in[18];
    const float* W_final = (const float*)d_in[19];
    const float* b_final = (const float*)d_in[20];
    const float* Wa1     = (const float*)d_in[21];
    const float* ba1     = (const float*)d_in[22];
    const float* Wa2     = (const float*)d_in[23];
    const float* ba2     = (const float*)d_in[24];
    float* out = (float*)d_out;

    float *p_xji, *p_tmp, *p_upd, *p_xkj2, *p_agg;
    uint32_t* p_Bf;
    cudaGetSymbolAddress((void**)&p_xji,  g_xji);
    cudaGetSymbolAddress((void**)&p_tmp,  g_tmp);
    cudaGetSymbolAddress((void**)&p_upd,  g_upd);
    cudaGetSymbolAddress((void**)&p_xkj2, g_xkj2);
    cudaGetSymbolAddress((void**)&p_agg,  g_agg);
    cudaGetSymbolAddress((void**)&p_Bf,   g_Bf);

    const int GB = E_EDGES / 128;     // 2048
    const int SM_K128 = 128*128*4;    // 65536
    const int SM_K64  = 128*64*4;     // 32768

    cudaFuncSetAttribute((const void*)gemm_mma3<128,128,false,false>, cudaFuncAttributeMaxDynamicSharedMemorySize, SM_K128);
    cudaFuncSetAttribute((const void*)gemm_mma3<128,128,true ,false>, cudaFuncAttributeMaxDynamicSharedMemorySize, SM_K128);
    cudaFuncSetAttribute((const void*)gemm_mma3<128,128,false,true >, cudaFuncAttributeMaxDynamicSharedMemorySize, SM_K128);
    cudaFuncSetAttribute((const void*)gemm_mma3<64 ,128,false,false>, cudaFuncAttributeMaxDynamicSharedMemorySize, SM_K128);
    cudaFuncSetAttribute((const void*)gemm_mma3<128,64 ,false,true >, cudaFuncAttributeMaxDynamicSharedMemorySize, SM_K64);
    cudaFuncSetAttribute((const void*)resid_mma3, cudaFuncAttributeMaxDynamicSharedMemorySize, SM_K128);

    // precompute: fused rbf weight + all B fragments + zero agg
    fuse_wr_kernel<<<3, 256>>>(W_rbf1, W_rbf2);
    zero_agg_kernel<<<(E_EDGES*INT_EMB/4)/256, 256>>>();

    stage_Bg<<<128, 128>>>(W_ji,    p_Bf + OFF_JI,   128, 128);
    stage_Bg<<<128, 128>>>(W_kj,    p_Bf + OFF_KJ,   128, 128);
    stage_Bg<<<64 , 128>>>(W_down,  p_Bf + OFF_DOWN, 128, 64);
    stage_Bg<<<64 , 128>>>(W_up,    p_Bf + OFF_UP,   64 , 128);
    stage_Bg<<<128, 128>>>(Wb1,     p_Bf + OFF_B1,   128, 128);
    stage_Bg<<<128, 128>>>(Wb2,     p_Bf + OFF_B2,   128, 128);
    stage_Bg<<<128, 128>>>(W_final, p_Bf + OFF_FIN,  128, 128);
    stage_Bg<<<128, 128>>>(Wa1,           p_Bf + OFF_A10, 128, 128);
    stage_Bg<<<128, 128>>>(Wa2,           p_Bf + OFF_A20, 128, 128);
    stage_Bg<<<128, 128>>>(Wa1 + 128*128, p_Bf + OFF_A11, 128, 128);
    stage_Bg<<<128, 128>>>(Wa2 + 128*128, p_Bf + OFF_A21, 128, 128);

    // x_ji = silu(m @ W_ji + b_ji)
    gemm_mma3<128,128,false,false><<<GB,256,SM_K128>>>(m, p_Bf + OFF_JI, b_ji, nullptr, nullptr, p_xji);
    // xkjm = silu(m @ W_kj + b_kj) * rbf_env
    gemm_mma3<128,128,true ,false><<<GB,256,SM_K128>>>(m, p_Bf + OFF_KJ, b_kj, nullptr, rbf, p_tmp);
    // x_kj2 = silu(xkjm @ W_down)
    gemm_mma3<64 ,128,false,false><<<GB,256,SM_K128>>>(p_tmp, p_Bf + OFF_DOWN, nullptr, nullptr, nullptr, p_xkj2);

    // triplet message + segment sum
    triplet_kernel<<<4096, 256>>>(sbf, src_idx, dst_idx, W_sbf1, W_sbf2);

    // upd = x_ji + silu(agg @ W_up)
    gemm_mma3<128,64 ,false,true ><<<GB,256,SM_K64>>>(p_agg, p_Bf + OFF_UP, nullptr, p_xji, nullptr, p_upd);
    // residual-before (N_BEFORE=1), in-place
    resid_mma3<<<GB,256,SM_K128>>>(p_upd, p_Bf + OFF_B1, bb1, p_Bf + OFF_B2, bb2, p_upd);
    // final: out = m + silu(upd @ W_final + b_final)
    gemm_mma3<128,128,false,true ><<<GB,256,SM_K128>>>(p_upd, p_Bf + OFF_FIN, b_final, m, nullptr, out);
    // residual-after (N_AFTER=2), in-place on out
    resid_mma3<<<GB,256,SM_K128>>>(out, p_Bf + OFF_A10, ba1,       p_Bf + OFF_A20, ba2,       out);
    resid_mma3<<<GB,256,SM_K128>>>(out, p_Bf + OFF_A11, ba1 + 128, p_Bf + OFF_A21, ba2 + 128, out);
}